// round 4
// baseline (speedup 1.0000x reference)
#include <cuda_runtime.h>

// Problem constants (fixed shapes)
#define Kc   100
#define Dc   64
#define TPB  256          // threads per block (8 warps)
#define WPB  8            // warps per block
#define NBLK 152          // ~one block per SM on GB300
#define TOTW (NBLK * WPB) // 1216 total warps

// Global scratch (allocation-free: __device__ globals)
__device__ float g_S1[Kc * Dc];
__device__ float g_S2[Kc];
__device__ float g_cnt[Kc];

// ---------------------------------------------------------------------------
// Kernel 0: zero the accumulators (graph replays require re-zeroing)
// ---------------------------------------------------------------------------
__global__ void zero_kernel() {
    int i = blockIdx.x * blockDim.x + threadIdx.x;
    if (i < Kc * Dc) g_S1[i] = 0.f;
    if (i < Kc) { g_S2[i] = 0.f; g_cnt[i] = 0.f; }
}

// ---------------------------------------------------------------------------
// Kernel 1: single streaming pass.
// Warp-private shared tables, non-atomic LDS/FADD/STS RMW.
// Lane l owns dims {2l, 2l+1}; warp handles a contiguous chunk of points.
// Labels are int32 (JAX default x64-disabled: jnp.int64 -> int32).
// ---------------------------------------------------------------------------
__global__ __launch_bounds__(TPB, 1)
void pass1_kernel(const float* __restrict__ data,
                  const int* __restrict__ ci, int N) {
    extern __shared__ float sm[];
    const int tid  = threadIdx.x;
    const int w    = tid >> 5;
    const int lane = tid & 31;

    float* tbl = sm + w * (Kc * Dc);                    // [Kc][Dc] per warp
    float* sqt = sm + WPB * Kc * Dc + w * Kc;           // [Kc] per warp
    float* cnt = sm + WPB * Kc * Dc + WPB * Kc + w * Kc;

    const int SM_FLOATS = WPB * Kc * Dc + 2 * WPB * Kc; // 52800
    for (int i = tid; i < SM_FLOATS; i += TPB) sm[i] = 0.f;
    __syncthreads();

    const int gw    = blockIdx.x * WPB + w;
    const int chunk = (N + TOTW - 1) / TOTW;
    const int begin = gw * chunk;
    const int end   = min(N, begin + chunk);

    const float2* __restrict__ d2 = (const float2*)data;

    int p = begin;
    for (; p + 8 <= end; p += 8) {
        int    c[8];
        float2 v[8];
#pragma unroll
        for (int u = 0; u < 8; u++) {
            c[u] = ci[p + u];                 // broadcast load (all lanes same addr)
            v[u] = d2[(p + u) * 32 + lane];   // coalesced 256B/warp
        }
#pragma unroll
        for (int u = 0; u < 8; u++) {
            int idx = c[u] * Dc + 2 * lane;
            float2 s = *(float2*)&tbl[idx];
            s.x += v[u].x;
            s.y += v[u].y;
            *(float2*)&tbl[idx] = s;
            float sq = v[u].x * v[u].x + v[u].y * v[u].y;
#pragma unroll
            for (int o = 16; o > 0; o >>= 1)
                sq += __shfl_xor_sync(0xffffffffu, sq, o);
            if (lane == 0)  sqt[c[u]] += sq;
            if (lane == 16) cnt[c[u]] += 1.f;
        }
    }
    for (; p < end; p++) {
        int    c0 = ci[p];
        float2 v  = d2[p * 32 + lane];
        int idx = c0 * Dc + 2 * lane;
        float2 s = *(float2*)&tbl[idx];
        s.x += v.x;
        s.y += v.y;
        *(float2*)&tbl[idx] = s;
        float sq = v.x * v.x + v.y * v.y;
#pragma unroll
        for (int o = 16; o > 0; o >>= 1)
            sq += __shfl_xor_sync(0xffffffffu, sq, o);
        if (lane == 0)  sqt[c0] += sq;
        if (lane == 16) cnt[c0] += 1.f;
    }
    __syncthreads();

    // Block-level combine of the 8 warp tables, then one atomicAdd per slot.
    for (int i = tid; i < Kc * Dc; i += TPB) {
        float s = 0.f;
#pragma unroll
        for (int ww = 0; ww < WPB; ww++) s += sm[ww * Kc * Dc + i];
        atomicAdd(&g_S1[i], s);
    }
    for (int i = tid; i < Kc; i += TPB) {
        float s = 0.f, cs = 0.f;
#pragma unroll
        for (int ww = 0; ww < WPB; ww++) {
            s  += sm[WPB * Kc * Dc + ww * Kc + i];
            cs += sm[WPB * Kc * Dc + WPB * Kc + ww * Kc + i];
        }
        atomicAdd(&g_S2[i], s);
        atomicAdd(&g_cnt[i], cs);
    }
}

// ---------------------------------------------------------------------------
// Kernel 2: finalize — centroids, Si, pairwise distances, DB index.
// A stored transposed [d][c] in smem so lane-consecutive c is conflict-free.
// ---------------------------------------------------------------------------
__global__ void finalize_kernel(float* __restrict__ out) {
    __shared__ float At[Dc * Kc];   // transposed centroids [d][c]
    __shared__ float Si[Kc];
    __shared__ float pmax[4][128];

    const int tid = threadIdx.x;    // 512 threads

    for (int i = tid; i < Kc * Dc; i += blockDim.x) {
        int c = i / Dc, d = i - c * Dc;
        At[d * Kc + c] = (0.001f + g_S1[i]) / (1.0f + g_cnt[c]);
    }
    __syncthreads();

    if (tid < Kc) {
        float nrm = 0.f, sa = 0.f;
#pragma unroll
        for (int d = 0; d < Dc; d++) {
            float a = At[d * Kc + tid];
            nrm += a * a;
            sa  += a;
        }
        float n  = g_cnt[tid];
        float cs = 1.f + n;
        // dot(A, S1) = cs*|A|^2 - 0.001*sum(A)   (since S1 = A*cs - 0.001 per dim)
        float dot = cs * nrm - 0.001f * sa;
        float val = (0.001f + g_S2[tid] - 2.f * dot + n * nrm) / cs;
        Si[tid] = sqrtf(fmaxf(val, 0.f));
    }
    __syncthreads();

    // Row-wise max of Rij; 4 thread-groups split the j range.
    const int c = tid & 127;
    const int g = tid >> 7;       // 0..3
    float m = 0.f;
    if (c < Kc) {
        const int j0 = g * 25, j1 = j0 + 25;
        const float sic = Si[c];
        for (int j = j0; j < j1; j++) {
            if (j == c) continue;
            float ss = 0.f;
#pragma unroll
            for (int d = 0; d < Dc; d++) {
                float df = At[d * Kc + c] - At[d * Kc + j];
                ss += df * df;
            }
            float r = (sic + Si[j]) / sqrtf(ss);
            m = fmaxf(m, r);
        }
    }
    pmax[g][c] = m;
    __syncthreads();

    if (tid < Kc) {
        float mm = fmaxf(fmaxf(pmax[0][tid], pmax[1][tid]),
                         fmaxf(pmax[2][tid], pmax[3][tid]));
        Si[tid] = mm;   // reuse
    }
    __syncthreads();

    if (tid == 0) {
        float s = 0.f;
        for (int cc = 0; cc < Kc; cc++) s += Si[cc];
        out[0] = s / (float)Kc;
    }
}

// ---------------------------------------------------------------------------
extern "C" void kernel_launch(void* const* d_in, const int* in_sizes, int n_in,
                              void* d_out, int out_size) {
    const float* data = (const float*)d_in[0];
    const int*   clus = (const int*)d_in[1];   // int32 labels (JAX x64 disabled)
    const int N = in_sizes[1];                 // 2,000,000

    const size_t smem = (size_t)(WPB * Kc * Dc + 2 * WPB * Kc) * sizeof(float); // 211,200 B
    cudaFuncSetAttribute(pass1_kernel,
                         cudaFuncAttributeMaxDynamicSharedMemorySize, (int)smem);

    zero_kernel<<<(Kc * Dc + 255) / 256, 256>>>();
    pass1_kernel<<<NBLK, TPB, smem>>>(data, clus, N);
    finalize_kernel<<<1, 512>>>((float*)d_out);
}

// round 5
// speedup vs baseline: 1.7068x; 1.7068x over previous
#include <cuda_runtime.h>

// Problem constants (fixed shapes)
#define Kc    100
#define Dc    64
#define TPB   128          // threads per block (4 warps)
#define WPB   4            // warps per block
#define NBLK  152          // ~one block per SM on GB300
#define TOTW  (NBLK * WPB) // 608 total warps
#define ROWF  128          // floats per cluster row: 32 lanes x float4
#define TBLF  (Kc * ROWF)  // 12800 floats per warp table
#define UNR   16           // batch size (double-buffered)

// Global scratch (allocation-free: __device__ globals, zero-init at load;
// finalize_kernel re-zeroes them after use so graph replays stay clean)
__device__ float g_S1[Kc * Dc];
__device__ float g_S2[Kc];
__device__ float g_cnt[Kc];

// ---------------------------------------------------------------------------
// Kernel 1: single streaming pass.
// Per-warp table [Kc][128]: lane l owns float4 (sum_2l, sum_2l+1, sq, cnt).
// ONE LDS.128/STS.128 RMW chain per point; no shuffles, no scalar RMWs.
// ---------------------------------------------------------------------------
__global__ __launch_bounds__(TPB, 1)
void pass1_kernel(const float* __restrict__ data,
                  const int* __restrict__ ci, int N) {
    extern __shared__ float sm[];
    const int tid  = threadIdx.x;
    const int w    = tid >> 5;
    const int lane = tid & 31;

    float* tbl = sm + w * TBLF;

    for (int i = tid; i < WPB * TBLF; i += TPB) sm[i] = 0.f;
    __syncthreads();

    const int gw    = blockIdx.x * WPB + w;
    const int chunk = (N + TOTW - 1) / TOTW;
    const int begin = gw * chunk;
    const int end   = min(N, begin + chunk);

    const float2* __restrict__ d2 = (const float2*)data;
    const int slot_off = 4 * lane;

    int    c_a[UNR], c_b[UNR];
    float2 v_a[UNR], v_b[UNR];

    const int nfull = (end - begin) / UNR;
    int p = begin;

    if (nfull > 0) {
#pragma unroll
        for (int u = 0; u < UNR; u++) {
            c_a[u] = ci[p + u];
            v_a[u] = d2[(p + u) * 32 + lane];
        }
    }
    for (int b = 0; b < nfull; b++) {
        const int pn = p + UNR;
        if (b + 1 < nfull) {
#pragma unroll
            for (int u = 0; u < UNR; u++) {       // prefetch next batch
                c_b[u] = ci[pn + u];
                v_b[u] = d2[(pn + u) * 32 + lane];
            }
        }
#pragma unroll
        for (int u = 0; u < UNR; u++) {           // single RMW chain per point
            float4* slot = (float4*)&tbl[c_a[u] * ROWF + slot_off];
            float4 s = *slot;
            const float2 v = v_a[u];
            s.x += v.x;
            s.y += v.y;
            s.z = fmaf(v.x, v.x, s.z);
            s.z = fmaf(v.y, v.y, s.z);
            s.w += 1.0f;
            *slot = s;
        }
#pragma unroll
        for (int u = 0; u < UNR; u++) { c_a[u] = c_b[u]; v_a[u] = v_b[u]; }
        p = pn;
    }
    for (; p < end; p++) {                        // tail
        const int c0 = ci[p];
        const float2 v = d2[p * 32 + lane];
        float4* slot = (float4*)&tbl[c0 * ROWF + slot_off];
        float4 s = *slot;
        s.x += v.x;
        s.y += v.y;
        s.z = fmaf(v.x, v.x, s.z);
        s.z = fmaf(v.y, v.y, s.z);
        s.w += 1.0f;
        *slot = s;
    }
    __syncthreads();

    // Combine the 4 warp tables, flush sums to global.
    for (int i = tid; i < TBLF; i += TPB) {
        float s = sm[i] + sm[TBLF + i] + sm[2 * TBLF + i] + sm[3 * TBLF + i];
        sm[i] = s;
        const int c = i >> 7;        // cluster
        const int j = i & 127;       // within-row
        const int m = j & 3;
        if (m < 2) {
            const int d = ((j >> 2) << 1) + m;
            atomicAdd(&g_S1[c * Dc + d], s);
        }
    }
    __syncthreads();

    // Per-cluster reduce of the 32 sq/cnt partials (rotated to dodge banks).
    if (tid < Kc) {
        float sq = 0.f, ct = 0.f;
#pragma unroll
        for (int li = 0; li < 32; li++) {
            const int l = (li + tid) & 31;
            sq += sm[tid * ROWF + 4 * l + 2];
            ct += sm[tid * ROWF + 4 * l + 3];
        }
        atomicAdd(&g_S2[tid], sq);
        atomicAdd(&g_cnt[tid], ct * 0.03125f);   // 32 lanes each added 1.0
    }
}

// ---------------------------------------------------------------------------
// Kernel 2: finalize — centroids, Si, pairwise distances, DB index.
// Also re-zeroes the global accumulators for the next graph replay.
// ---------------------------------------------------------------------------
__global__ void finalize_kernel(float* __restrict__ out) {
    __shared__ float At[Dc * Kc];   // transposed centroids [d][c]
    __shared__ float Si[Kc];
    __shared__ float pmax[4][128];

    const int tid = threadIdx.x;    // 512 threads

    for (int i = tid; i < Kc * Dc; i += blockDim.x) {
        const int c = i / Dc, d = i - c * Dc;
        At[d * Kc + c] = (0.001f + g_S1[i]) / (1.0f + g_cnt[c]);
    }
    __syncthreads();

    if (tid < Kc) {
        float nrm = 0.f, sa = 0.f;
#pragma unroll
        for (int d = 0; d < Dc; d++) {
            const float a = At[d * Kc + tid];
            nrm += a * a;
            sa  += a;
        }
        const float n  = g_cnt[tid];
        const float cs = 1.f + n;
        // dot(A, S1) = cs*|A|^2 - 0.001*sum(A)  (since S1 = A*cs - 0.001 per dim)
        const float dot = cs * nrm - 0.001f * sa;
        const float val = (0.001f + g_S2[tid] - 2.f * dot + n * nrm) / cs;
        Si[tid] = sqrtf(fmaxf(val, 0.f));
    }
    __syncthreads();

    // All global accumulators consumed -> re-zero for next replay.
    for (int i = tid; i < Kc * Dc; i += blockDim.x) g_S1[i] = 0.f;
    if (tid < Kc) { g_S2[tid] = 0.f; g_cnt[tid] = 0.f; }

    // Row-wise max of Rij; 4 thread-groups split the j range.
    const int c = tid & 127;
    const int g = tid >> 7;          // 0..3
    float m = 0.f;
    if (c < Kc) {
        const int j0 = g * 25, j1 = j0 + 25;
        const float sic = Si[c];
        for (int j = j0; j < j1; j++) {
            if (j == c) continue;
            float ss = 0.f;
#pragma unroll
            for (int d = 0; d < Dc; d++) {
                const float df = At[d * Kc + c] - At[d * Kc + j];
                ss += df * df;
            }
            const float r = (sic + Si[j]) / sqrtf(ss);
            m = fmaxf(m, r);
        }
    }
    pmax[g][c] = m;
    __syncthreads();

    if (tid < Kc) {
        const float mm = fmaxf(fmaxf(pmax[0][tid], pmax[1][tid]),
                               fmaxf(pmax[2][tid], pmax[3][tid]));
        Si[tid] = mm;   // reuse
    }
    __syncthreads();

    if (tid == 0) {
        float s = 0.f;
        for (int cc = 0; cc < Kc; cc++) s += Si[cc];
        out[0] = s / (float)Kc;
    }
}

// ---------------------------------------------------------------------------
extern "C" void kernel_launch(void* const* d_in, const int* in_sizes, int n_in,
                              void* d_out, int out_size) {
    const float* data = (const float*)d_in[0];
    const int*   clus = (const int*)d_in[1];   // int32 labels (JAX x64 disabled)
    const int N = in_sizes[1];                 // 2,000,000

    const size_t smem = (size_t)(WPB * TBLF) * sizeof(float);   // 204,800 B
    cudaFuncSetAttribute(pass1_kernel,
                         cudaFuncAttributeMaxDynamicSharedMemorySize, (int)smem);

    pass1_kernel<<<NBLK, TPB, smem>>>(data, clus, N);
    finalize_kernel<<<1, 512>>>((float*)d_out);
}

// round 6
// speedup vs baseline: 1.8950x; 1.1102x over previous
#include <cuda_runtime.h>

// Problem constants (fixed shapes)
#define Kc    100
#define Dc    64
#define TPB   128          // 4 warps
#define WPB   4
#define NBLK  152
#define TOTW  (NBLK * WPB) // 608 warps
#define ROWF  128          // floats per cluster row: 32 lanes x float4 slot
#define TBLF  (Kc * ROWF)  // 12800 floats per warp table
#define UNR   8            // batch size

// Global scratch (zero-init at load; re-zeroed by finpre each replay)
__device__ float g_S1[Kc * Dc];
__device__ float g_S2[Kc];
__device__ float g_cnt[Kc];
__device__ float g_At[Dc * Kc];   // centroids, transposed [d][c]
__device__ float g_Si[Kc];

// ---- packed f32x2 helpers (sm_103a; ptxas won't auto-emit these) ----------
__device__ __forceinline__ unsigned long long addx2(unsigned long long a,
                                                    unsigned long long b) {
    unsigned long long r;
    asm("add.rn.f32x2 %0, %1, %2;" : "=l"(r) : "l"(a), "l"(b));
    return r;
}
__device__ __forceinline__ unsigned long long mulx2(unsigned long long a,
                                                    unsigned long long b) {
    unsigned long long r;
    asm("mul.rn.f32x2 %0, %1, %2;" : "=l"(r) : "l"(a), "l"(b));
    return r;
}
__device__ __forceinline__ unsigned smem_u32(const void* p) {
    unsigned r;
    asm("{ .reg .u64 t; cvta.to.shared.u64 t, %1; cvt.u32.u64 %0, t; }"
        : "=r"(r) : "l"(p));
    return r;
}

// ---------------------------------------------------------------------------
// Kernel A: label histogram -> g_cnt (counts no longer live in pass1's slot)
// ---------------------------------------------------------------------------
__global__ void hist_kernel(const int* __restrict__ ci, int N) {
    __shared__ int h[Kc];
    const int tid = threadIdx.x;
    if (tid < Kc) h[tid] = 0;
    __syncthreads();
    const int4* c4 = (const int4*)ci;
    const int n4 = N >> 2;
    for (int i = blockIdx.x * blockDim.x + tid; i < n4; i += gridDim.x * blockDim.x) {
        int4 v = c4[i];
        atomicAdd(&h[v.x], 1); atomicAdd(&h[v.y], 1);
        atomicAdd(&h[v.z], 1); atomicAdd(&h[v.w], 1);
    }
    if (blockIdx.x == 0 && tid == 0)
        for (int i = n4 << 2; i < N; i++) atomicAdd(&g_cnt[ci[i]], 1.f);
    __syncthreads();
    if (tid < Kc) atomicAdd(&g_cnt[tid], (float)h[tid]);
}

// ---------------------------------------------------------------------------
// Kernel B: main streaming pass.
// Per-warp table [Kc][128]: lane l slot = (sum_2l, sum_2l+1, sq_2l, sq_2l+1).
// Batched LDS-before-STS (UNR=8) with clash fast-path; packed f32x2 math;
// 3-buffer LDG prefetch rotation (distance 2).
// ---------------------------------------------------------------------------
__global__ __launch_bounds__(TPB, 1)
void pass1_kernel(const float* __restrict__ data,
                  const int* __restrict__ ci, int N) {
    extern __shared__ float sm[];
    const int tid  = threadIdx.x;
    const int w    = tid >> 5;
    const int lane = tid & 31;

    float4* z = (float4*)sm;
    for (int i = tid; i < (WPB * TBLF) >> 2; i += TPB)
        z[i] = make_float4(0.f, 0.f, 0.f, 0.f);
    __syncthreads();

    const unsigned sbase = smem_u32(sm) + (unsigned)w * (TBLF * 4) + (unsigned)lane * 16;
    const int gw    = blockIdx.x * WPB + w;
    const int chunk = (N + TOTW - 1) / TOTW;
    const int begin = gw * chunk;
    const int end   = min(N, begin + chunk);

    const unsigned long long* __restrict__ d2 = (const unsigned long long*)data;

    int                cA[UNR], cB[UNR], cC[UNR];
    unsigned long long vA[UNR], vB[UNR], vC[UNR];

    auto stage = [&](int* cx, unsigned long long* vx, int base) {
#pragma unroll
        for (int u = 0; u < UNR; u++) {
            cx[u] = ci[base + u];
            vx[u] = d2[(base + u) * 32 + lane];
        }
    };

    auto process = [&](int* c, unsigned long long* v) {
        unsigned long long q[UNR];
        unsigned addr[UNR];
#pragma unroll
        for (int u = 0; u < UNR; u++) {
            q[u]    = mulx2(v[u], v[u]);
            addr[u] = sbase + ((unsigned)c[u] << 9);
        }
        bool clash = false;
#pragma unroll
        for (int u = 0; u < UNR - 1; u++)
#pragma unroll
            for (int j = u + 1; j < UNR; j++) clash |= (c[u] == c[j]);

        if (!clash) {   // all distinct clusters: batch LDS before STS (legal)
            unsigned long long a0[UNR], a1[UNR];
#pragma unroll
            for (int u = 0; u < UNR; u++)
                asm volatile("ld.shared.v2.u64 {%0,%1},[%2];"
                             : "=l"(a0[u]), "=l"(a1[u]) : "r"(addr[u]));
#pragma unroll
            for (int u = 0; u < UNR; u++) {
                a0[u] = addx2(a0[u], v[u]);
                a1[u] = addx2(a1[u], q[u]);
            }
#pragma unroll
            for (int u = 0; u < UNR; u++)
                asm volatile("st.shared.v2.u64 [%0],{%1,%2};"
                             :: "r"(addr[u]), "l"(a0[u]), "l"(a1[u]) : "memory");
        } else {        // rare: merge duplicates forward, serial chains on live
            bool live[UNR];
#pragma unroll
            for (int u = 0; u < UNR; u++) live[u] = true;
#pragma unroll
            for (int u = 0; u < UNR - 1; u++) {
                bool moved = false;
#pragma unroll
                for (int j = u + 1; j < UNR; j++) {
                    bool m = (c[u] == c[j]) && !moved;
                    if (m) { v[j] = addx2(v[j], v[u]); q[j] = addx2(q[j], q[u]); }
                    moved = moved || m;
                }
                live[u] = !moved;
            }
#pragma unroll
            for (int u = 0; u < UNR; u++) {
                if (live[u]) {
                    unsigned long long a0, a1;
                    asm volatile("ld.shared.v2.u64 {%0,%1},[%2];"
                                 : "=l"(a0), "=l"(a1) : "r"(addr[u]));
                    a0 = addx2(a0, v[u]);
                    a1 = addx2(a1, q[u]);
                    asm volatile("st.shared.v2.u64 [%0],{%1,%2};"
                                 :: "r"(addr[u]), "l"(a0), "l"(a1) : "memory");
                }
            }
        }
    };

    const int nb = (end - begin) / UNR;
    if (nb >= 1) stage(cA, vA, begin);
    if (nb >= 2) stage(cB, vB, begin + UNR);
    for (int b = 0; b < nb; b += 3) {
        if (b + 2 < nb) stage(cC, vC, begin + (b + 2) * UNR);
        process(cA, vA);
        if (b + 1 >= nb) break;
        if (b + 3 < nb) stage(cA, vA, begin + (b + 3) * UNR);
        process(cB, vB);
        if (b + 2 >= nb) break;
        if (b + 4 < nb) stage(cB, vB, begin + (b + 4) * UNR);
        process(cC, vC);
    }
    for (int p = begin + nb * UNR; p < end; p++) {   // tail (<8 points)
        const int c0 = ci[p];
        unsigned long long vv = d2[p * 32 + lane];
        unsigned long long qq = mulx2(vv, vv);
        const unsigned ad = sbase + ((unsigned)c0 << 9);
        unsigned long long a0, a1;
        asm volatile("ld.shared.v2.u64 {%0,%1},[%2];" : "=l"(a0), "=l"(a1) : "r"(ad));
        a0 = addx2(a0, vv);
        a1 = addx2(a1, qq);
        asm volatile("st.shared.v2.u64 [%0],{%1,%2};"
                     :: "r"(ad), "l"(a0), "l"(a1) : "memory");
    }
    __syncthreads();

    // Combine the 4 warp tables; flush S1, then per-cluster S2.
    for (int i = tid; i < TBLF; i += TPB) {
        float s = sm[i] + sm[TBLF + i] + sm[2 * TBLF + i] + sm[3 * TBLF + i];
        const int c = i >> 7, r = i & 127, m = r & 3, l = r >> 2;
        if (m < 2) atomicAdd(&g_S1[c * Dc + 2 * l + m], s);
        else       sm[i] = s;
    }
    __syncthreads();
    if (tid < Kc) {
        float sq = 0.f;
#pragma unroll
        for (int l = 0; l < 32; l++)
            sq += sm[tid * ROWF + 4 * l + 2] + sm[tid * ROWF + 4 * l + 3];
        atomicAdd(&g_S2[tid], sq);
    }
}

// ---------------------------------------------------------------------------
// Kernel C: centroids + Si; re-zero accumulators; init out.
// ---------------------------------------------------------------------------
__global__ void finpre_kernel(float* __restrict__ out) {
    __shared__ float At[Dc * Kc];   // [d][c]
    const int tid = threadIdx.x;    // 512
    for (int i = tid; i < Kc * Dc; i += blockDim.x) {
        const int c = i / Dc, d = i - c * Dc;
        const float a = (0.001f + g_S1[i]) / (1.0f + g_cnt[c]);
        At[d * Kc + c] = a;
        g_At[d * Kc + c] = a;
    }
    __syncthreads();
    if (tid < Kc) {
        float nrm = 0.f, sa = 0.f;
#pragma unroll
        for (int d = 0; d < Dc; d++) {
            const float a = At[d * Kc + tid];
            nrm += a * a;
            sa  += a;
        }
        const float n  = g_cnt[tid];
        const float cs = 1.f + n;
        // dot(A, S1) = cs*|A|^2 - 0.001*sum(A)  (S1 = A*cs - 0.001 per dim)
        const float dot = cs * nrm - 0.001f * sa;
        const float val = (0.001f + g_S2[tid] - 2.f * dot + n * nrm) / cs;
        g_Si[tid] = sqrtf(fmaxf(val, 0.f));
        g_S2[tid] = 0.f;
        g_cnt[tid] = 0.f;
    }
    __syncthreads();
    for (int i = tid; i < Kc * Dc; i += blockDim.x) g_S1[i] = 0.f;
    if (tid == 0) out[0] = 0.f;
}

// ---------------------------------------------------------------------------
// Kernel D: one block per cluster row; row-max of Rij; atomic sum of maxima.
// ---------------------------------------------------------------------------
__global__ void findb_kernel(float* __restrict__ out) {
    __shared__ float At[Dc * Kc];
    __shared__ float Sis[Kc];
    __shared__ float wmax[4];
    const int tid = threadIdx.x;    // 128
    const int c   = blockIdx.x;     // 0..99
    for (int i = tid; i < Dc * Kc; i += blockDim.x) At[i] = g_At[i];
    if (tid < Kc) Sis[tid] = g_Si[tid];
    __syncthreads();
    float m = 0.f;
    if (tid < Kc && tid != c) {
        const int j = tid;
        float ss = 0.f;
#pragma unroll
        for (int d = 0; d < Dc; d++) {
            const float df = At[d * Kc + c] - At[d * Kc + j];
            ss = fmaf(df, df, ss);
        }
        m = (Sis[c] + Sis[j]) / sqrtf(ss);
    }
#pragma unroll
    for (int o = 16; o > 0; o >>= 1) m = fmaxf(m, __shfl_xor_sync(~0u, m, o));
    if ((tid & 31) == 0) wmax[tid >> 5] = m;
    __syncthreads();
    if (tid == 0) {
        const float mm = fmaxf(fmaxf(wmax[0], wmax[1]), fmaxf(wmax[2], wmax[3]));
        atomicAdd(out, mm * (1.0f / (float)Kc));
    }
}

// ---------------------------------------------------------------------------
extern "C" void kernel_launch(void* const* d_in, const int* in_sizes, int n_in,
                              void* d_out, int out_size) {
    const float* data = (const float*)d_in[0];
    const int*   clus = (const int*)d_in[1];   // int32 labels (JAX x64 disabled)
    const int N = in_sizes[1];                 // 2,000,000

    const size_t smem = (size_t)(WPB * TBLF) * sizeof(float);   // 204,800 B
    cudaFuncSetAttribute(pass1_kernel,
                         cudaFuncAttributeMaxDynamicSharedMemorySize, (int)smem);

    hist_kernel  <<<NBLK, 256>>>(clus, N);          // 4 launches/replay:
    pass1_kernel <<<NBLK, TPB, smem>>>(data, clus, N); // ncu -s5 lands HERE
    finpre_kernel<<<1, 512>>>((float*)d_out);
    findb_kernel <<<Kc, 128>>>((float*)d_out);
}

// round 7
// speedup vs baseline: 2.3324x; 1.2308x over previous
#include <cuda_runtime.h>

// Problem constants (fixed shapes)
#define Kc    100
#define Dc    64
#define TPB   128          // 4 warps, 1 per SMSP
#define WPB   4
#define NBLK  152
#define TOTW  (NBLK * WPB) // 608 warps
#define ROWF  128          // floats per cluster row: 32 lanes x float4 slot
#define TBLF  (Kc * ROWF)  // 12800 floats per warp table
#define UNR   4            // points per batch
#define PIPE  8            // batches in flight (register pipeline depth)

// Global scratch (zero-init at load; re-zeroed by finpre each replay)
__device__ float g_S1[Kc * Dc];
__device__ float g_S2[Kc];
__device__ float g_cnt[Kc];
__device__ float g_At[Dc * Kc];   // centroids, transposed [d][c]
__device__ float g_Si[Kc];

// ---- packed f32x2 helpers (sm_103a; ptxas won't auto-emit these) ----------
__device__ __forceinline__ unsigned long long addx2(unsigned long long a,
                                                    unsigned long long b) {
    unsigned long long r;
    asm("add.rn.f32x2 %0, %1, %2;" : "=l"(r) : "l"(a), "l"(b));
    return r;
}
__device__ __forceinline__ unsigned long long mulx2(unsigned long long a,
                                                    unsigned long long b) {
    unsigned long long r;
    asm("mul.rn.f32x2 %0, %1, %2;" : "=l"(r) : "l"(a), "l"(b));
    return r;
}
__device__ __forceinline__ unsigned smem_u32(const void* p) {
    unsigned r;
    asm("{ .reg .u64 t; cvta.to.shared.u64 t, %1; cvt.u32.u64 %0, t; }"
        : "=r"(r) : "l"(p));
    return r;
}

// ---------------------------------------------------------------------------
// Kernel A: partial label histogram over [from,to) -> g_cnt.
// Split into 3 launches so pass1 is the 4th launch (ncu -s5 profiles it).
// ---------------------------------------------------------------------------
__global__ void hist_kernel(const int* __restrict__ ci, int from, int to) {
    __shared__ int h[Kc];
    const int tid = threadIdx.x;
    if (tid < Kc) h[tid] = 0;
    __syncthreads();
    for (int i = from + blockIdx.x * blockDim.x + tid; i < to;
         i += gridDim.x * blockDim.x)
        atomicAdd(&h[ci[i]], 1);
    __syncthreads();
    if (tid < Kc && h[tid]) atomicAdd(&g_cnt[tid], (float)h[tid]);
}

// ---------------------------------------------------------------------------
// Kernel B: main streaming pass.
// Per-warp table [Kc][128]: lane l slot = (sum_2l, sum_2l+1, sq_2l, sq_2l+1).
// UNR=4 batches, PIPE=8 register pipeline (~360 cyc prefetch lead),
// batched LDS-before-STS with clash fast path, packed f32x2 math.
// ---------------------------------------------------------------------------
__global__ __launch_bounds__(TPB, 1)
void pass1_kernel(const float* __restrict__ data,
                  const int* __restrict__ ci, int N) {
    extern __shared__ float sm[];
    const int tid  = threadIdx.x;
    const int w    = tid >> 5;
    const int lane = tid & 31;

    float4* z = (float4*)sm;
    for (int i = tid; i < (WPB * TBLF) >> 2; i += TPB)
        z[i] = make_float4(0.f, 0.f, 0.f, 0.f);
    __syncthreads();

    const unsigned sbase = smem_u32(sm) + (unsigned)w * (TBLF * 4)
                         + (unsigned)lane * 16;
    const int gw    = blockIdx.x * WPB + w;
    const int chunk = (((N + TOTW - 1) / TOTW) + 15) & ~15;  // 16-aligned
    const int begin = gw * chunk;
    const int end   = min(N, begin + chunk);

    const unsigned long long* __restrict__ d2 = (const unsigned long long*)data;

    int                cb[PIPE][UNR];
    unsigned long long vb[PIPE][UNR];

    auto stage = [&](int j, int base) {
        const int4 cc = *(const int4*)&ci[base];   // 16B-aligned (base mult 16... mult 4)
        cb[j][0] = cc.x; cb[j][1] = cc.y; cb[j][2] = cc.z; cb[j][3] = cc.w;
#pragma unroll
        for (int u = 0; u < UNR; u++)
            vb[j][u] = d2[(base + u) * 32 + lane];
    };

    auto process = [&](int j) {
        int* c = cb[j];
        unsigned long long* v = vb[j];
        unsigned long long q[UNR];
        unsigned addr[UNR];
#pragma unroll
        for (int u = 0; u < UNR; u++) {
            q[u]    = mulx2(v[u], v[u]);
            addr[u] = sbase + ((unsigned)c[u] << 9);
        }
        bool clash = false;
#pragma unroll
        for (int u = 0; u < UNR - 1; u++)
#pragma unroll
            for (int k = u + 1; k < UNR; k++) clash |= (c[u] == c[k]);

        if (!clash) {   // distinct clusters: batch all LDS before any STS
            unsigned long long a0[UNR], a1[UNR];
#pragma unroll
            for (int u = 0; u < UNR; u++)
                asm volatile("ld.shared.v2.u64 {%0,%1},[%2];"
                             : "=l"(a0[u]), "=l"(a1[u]) : "r"(addr[u]));
#pragma unroll
            for (int u = 0; u < UNR; u++) {
                a0[u] = addx2(a0[u], v[u]);
                a1[u] = addx2(a1[u], q[u]);
            }
#pragma unroll
            for (int u = 0; u < UNR; u++)
                asm volatile("st.shared.v2.u64 [%0],{%1,%2};"
                             :: "r"(addr[u]), "l"(a0[u]), "l"(a1[u]) : "memory");
        } else {        // rare (~6%): merge duplicates forward, serial chains
            bool live[UNR];
#pragma unroll
            for (int u = 0; u < UNR; u++) live[u] = true;
#pragma unroll
            for (int u = 0; u < UNR - 1; u++) {
                bool moved = false;
#pragma unroll
                for (int k = u + 1; k < UNR; k++) {
                    bool m = (c[u] == c[k]) && !moved;
                    if (m) { v[k] = addx2(v[k], v[u]); q[k] = addx2(q[k], q[u]); }
                    moved = moved || m;
                }
                live[u] = !moved;
            }
#pragma unroll
            for (int u = 0; u < UNR; u++) {
                if (live[u]) {
                    unsigned long long a0, a1;
                    asm volatile("ld.shared.v2.u64 {%0,%1},[%2];"
                                 : "=l"(a0), "=l"(a1) : "r"(addr[u]));
                    a0 = addx2(a0, v[u]);
                    a1 = addx2(a1, q[u]);
                    asm volatile("st.shared.v2.u64 [%0],{%1,%2};"
                                 :: "r"(addr[u]), "l"(a0), "l"(a1) : "memory");
                }
            }
        }
    };

    const int nb = (begin < end) ? (end - begin) / UNR : 0;

    // Prologue: fill the pipeline.
#pragma unroll
    for (int j = 0; j < PIPE; j++)
        if (j < nb) stage(j, begin + j * UNR);

    // Main: process batch b (buffer b%PIPE), immediately restage batch b+PIPE.
    int b = 0;
    for (; b + PIPE <= nb; b += PIPE) {
#pragma unroll
        for (int j = 0; j < PIPE; j++) {
            process(j);
            const int nxt = b + j + PIPE;
            if (nxt < nb) stage(j, begin + nxt * UNR);
        }
    }
    // Epilogue: drain remaining staged batches (b is a multiple of PIPE).
#pragma unroll
    for (int j = 0; j < PIPE; j++)
        if (b + j < nb) process(j);

    // Tail points (< UNR).
    for (int p = begin + nb * UNR; p < end; p++) {
        const int c0 = ci[p];
        unsigned long long vv = d2[p * 32 + lane];
        unsigned long long qq = mulx2(vv, vv);
        const unsigned ad = sbase + ((unsigned)c0 << 9);
        unsigned long long a0, a1;
        asm volatile("ld.shared.v2.u64 {%0,%1},[%2];" : "=l"(a0), "=l"(a1) : "r"(ad));
        a0 = addx2(a0, vv);
        a1 = addx2(a1, qq);
        asm volatile("st.shared.v2.u64 [%0],{%1,%2};"
                     :: "r"(ad), "l"(a0), "l"(a1) : "memory");
    }
    __syncthreads();

    // Combine the 4 warp tables; flush S1, then per-cluster S2.
    for (int i = tid; i < TBLF; i += TPB) {
        float s = sm[i] + sm[TBLF + i] + sm[2 * TBLF + i] + sm[3 * TBLF + i];
        const int c = i >> 7, r = i & 127, m = r & 3, l = r >> 2;
        if (m < 2) atomicAdd(&g_S1[c * Dc + 2 * l + m], s);
        else       sm[i] = s;
    }
    __syncthreads();
    if (tid < Kc) {
        float sq = 0.f;
#pragma unroll
        for (int l = 0; l < 32; l++)
            sq += sm[tid * ROWF + 4 * l + 2] + sm[tid * ROWF + 4 * l + 3];
        atomicAdd(&g_S2[tid], sq);
    }
}

// ---------------------------------------------------------------------------
// Kernel C: centroids + Si; re-zero accumulators; init out.
// ---------------------------------------------------------------------------
__global__ void finpre_kernel(float* __restrict__ out) {
    __shared__ float At[Dc * Kc];   // [d][c]
    const int tid = threadIdx.x;    // 512
    for (int i = tid; i < Kc * Dc; i += blockDim.x) {
        const int c = i / Dc, d = i - c * Dc;
        const float a = (0.001f + g_S1[i]) / (1.0f + g_cnt[c]);
        At[d * Kc + c] = a;
        g_At[d * Kc + c] = a;
    }
    __syncthreads();
    if (tid < Kc) {
        float nrm = 0.f, sa = 0.f;
#pragma unroll
        for (int d = 0; d < Dc; d++) {
            const float a = At[d * Kc + tid];
            nrm += a * a;
            sa  += a;
        }
        const float n  = g_cnt[tid];
        const float cs = 1.f + n;
        // dot(A, S1) = cs*|A|^2 - 0.001*sum(A)  (S1 = A*cs - 0.001 per dim)
        const float dot = cs * nrm - 0.001f * sa;
        const float val = (0.001f + g_S2[tid] - 2.f * dot + n * nrm) / cs;
        g_Si[tid] = sqrtf(fmaxf(val, 0.f));
        g_S2[tid] = 0.f;
        g_cnt[tid] = 0.f;
    }
    __syncthreads();
    for (int i = tid; i < Kc * Dc; i += blockDim.x) g_S1[i] = 0.f;
    if (tid == 0) out[0] = 0.f;
}

// ---------------------------------------------------------------------------
// Kernel D: one block per cluster row; row-max of Rij; atomic sum of maxima.
// ---------------------------------------------------------------------------
__global__ void findb_kernel(float* __restrict__ out) {
    __shared__ float At[Dc * Kc];
    __shared__ float Sis[Kc];
    __shared__ float wmax[4];
    const int tid = threadIdx.x;    // 128
    const int c   = blockIdx.x;     // 0..99
    for (int i = tid; i < Dc * Kc; i += blockDim.x) At[i] = g_At[i];
    if (tid < Kc) Sis[tid] = g_Si[tid];
    __syncthreads();
    float m = 0.f;
    if (tid < Kc && tid != c) {
        const int j = tid;
        float ss = 0.f;
#pragma unroll
        for (int d = 0; d < Dc; d++) {
            const float df = At[d * Kc + c] - At[d * Kc + j];
            ss = fmaf(df, df, ss);
        }
        m = (Sis[c] + Sis[j]) / sqrtf(ss);
    }
#pragma unroll
    for (int o = 16; o > 0; o >>= 1) m = fmaxf(m, __shfl_xor_sync(~0u, m, o));
    if ((tid & 31) == 0) wmax[tid >> 5] = m;
    __syncthreads();
    if (tid == 0) {
        const float mm = fmaxf(fmaxf(wmax[0], wmax[1]), fmaxf(wmax[2], wmax[3]));
        atomicAdd(out, mm * (1.0f / (float)Kc));
    }
}

// ---------------------------------------------------------------------------
extern "C" void kernel_launch(void* const* d_in, const int* in_sizes, int n_in,
                              void* d_out, int out_size) {
    const float* data = (const float*)d_in[0];
    const int*   clus = (const int*)d_in[1];   // int32 labels (JAX x64 disabled)
    const int N = in_sizes[1];                 // 2,000,000

    const size_t smem = (size_t)(WPB * TBLF) * sizeof(float);   // 204,800 B
    cudaFuncSetAttribute(pass1_kernel,
                         cudaFuncAttributeMaxDynamicSharedMemorySize, (int)smem);

    const int t1 = N / 3, t2 = (2 * N) / 3;
    hist_kernel  <<<NBLK, 256>>>(clus, 0,  t1);   // launches 1-3: histogram
    hist_kernel  <<<NBLK, 256>>>(clus, t1, t2);
    hist_kernel  <<<NBLK, 256>>>(clus, t2, N);
    pass1_kernel <<<NBLK, TPB, smem>>>(data, clus, N);  // 4th: ncu lands HERE
    finpre_kernel<<<1, 512>>>((float*)d_out);
    findb_kernel <<<Kc, 128>>>((float*)d_out);
}

// round 8
// speedup vs baseline: 2.6904x; 1.1535x over previous
#include <cuda_runtime.h>

// Problem constants (fixed shapes)
#define Kc    100
#define Dc    64
#define TPB   256          // 8 warps, 2 per SMSP
#define WPB   8
#define NPAIR 4            // warp pairs per block
#define NBLK  152
#define TOTP  (NBLK * NPAIR) // 608 warp pairs
#define WTBLF (Kc * 64)    // floats per warp table: Kc rows x 32 lanes x (sum,sq)
#define UNR   4            // points per batch
#define PIPE  8            // batches in flight per warp

// Global scratch (zero-init at load; re-zeroed by findb each replay)
__device__ float g_S1[Kc * Dc];
__device__ float g_S2[Kc];
__device__ float g_cnt[Kc];
__device__ float g_At[Dc * Kc];   // centroids, transposed [d][c]
__device__ float g_Si[Kc];

__device__ __forceinline__ unsigned smem_u32(const void* p) {
    unsigned r;
    asm("{ .reg .u64 t; cvta.to.shared.u64 t, %1; cvt.u32.u64 %0, t; }"
        : "=r"(r) : "l"(p));
    return r;
}

// ---------------------------------------------------------------------------
// Kernel A: partial label histogram over [from,to) -> g_cnt.
// 3 launches so pass1 stays the 4th launch (ncu lands on it).
// ---------------------------------------------------------------------------
__global__ void hist_kernel(const int* __restrict__ ci, int from, int to) {
    __shared__ int h[Kc];
    const int tid = threadIdx.x;
    if (tid < Kc) h[tid] = 0;
    __syncthreads();
    for (int i = from + blockIdx.x * blockDim.x + tid; i < to;
         i += gridDim.x * blockDim.x)
        atomicAdd(&h[ci[i]], 1);
    __syncthreads();
    if (tid < Kc && h[tid]) atomicAdd(&g_cnt[tid], (float)h[tid]);
}

// ---------------------------------------------------------------------------
// Kernel B: main streaming pass, dim-split warp pairs.
// Warp pair (2w,2w+1) shares a point chunk; warp half=w&1 owns dims
// [half*32, half*32+32); lane l owns ONE dim -> 8B slot (sum, sq).
// Table 25.6 KB/warp -> 8 warps @ 204.8 KB smem (2 warps/SMSP).
// ---------------------------------------------------------------------------
__global__ __launch_bounds__(TPB, 1)
void pass1_kernel(const float* __restrict__ data,
                  const int* __restrict__ ci, int N) {
    extern __shared__ float sm[];
    const int tid  = threadIdx.x;
    const int w    = tid >> 5;
    const int lane = tid & 31;
    const int half = w & 1;

    float4* z = (float4*)sm;
    for (int i = tid; i < (WPB * WTBLF) >> 2; i += TPB)
        z[i] = make_float4(0.f, 0.f, 0.f, 0.f);
    __syncthreads();

    const unsigned sbase = smem_u32(sm) + (unsigned)w * (WTBLF * 4)
                         + (unsigned)lane * 8;
    const int gp    = blockIdx.x * NPAIR + (w >> 1);
    const int chunk = (((N + TOTP - 1) / TOTP) + 15) & ~15;  // 16-aligned
    const int begin = gp * chunk;
    const int end   = min(N, begin + chunk);

    const int doff = half * 32 + lane;   // this thread's dim within a point

    int   cb[PIPE][UNR];
    float vb[PIPE][UNR];

    auto stage = [&](int j, int base) {
        const int4 cc = *(const int4*)&ci[base];   // base is 4-aligned
        cb[j][0] = cc.x; cb[j][1] = cc.y; cb[j][2] = cc.z; cb[j][3] = cc.w;
#pragma unroll
        for (int u = 0; u < UNR; u++)
            vb[j][u] = data[(base + u) * 64 + doff];   // 128B/warp coalesced
    };

    auto process = [&](int j) {
        int*   c = cb[j];
        float* v = vb[j];
        float  q[UNR];
        unsigned addr[UNR];
#pragma unroll
        for (int u = 0; u < UNR; u++) {
            q[u]    = v[u] * v[u];
            addr[u] = sbase + ((unsigned)c[u] << 8);
        }
        bool clash = false;
#pragma unroll
        for (int u = 0; u < UNR - 1; u++)
#pragma unroll
            for (int k = u + 1; k < UNR; k++) clash |= (c[u] == c[k]);

        if (!clash) {   // distinct clusters: batch all LDS before any STS
            float a0[UNR], a1[UNR];
#pragma unroll
            for (int u = 0; u < UNR; u++)
                asm volatile("ld.shared.v2.f32 {%0,%1},[%2];"
                             : "=f"(a0[u]), "=f"(a1[u]) : "r"(addr[u]));
#pragma unroll
            for (int u = 0; u < UNR; u++) {
                a0[u] += v[u];
                a1[u] += q[u];
            }
#pragma unroll
            for (int u = 0; u < UNR; u++)
                asm volatile("st.shared.v2.f32 [%0],{%1,%2};"
                             :: "r"(addr[u]), "f"(a0[u]), "f"(a1[u]) : "memory");
        } else {        // rare (~6%): merge duplicates forward, serial chains
            bool live[UNR];
#pragma unroll
            for (int u = 0; u < UNR; u++) live[u] = true;
#pragma unroll
            for (int u = 0; u < UNR - 1; u++) {
                bool moved = false;
#pragma unroll
                for (int k = u + 1; k < UNR; k++) {
                    bool m = (c[u] == c[k]) && !moved;
                    if (m) { v[k] += v[u]; q[k] += q[u]; }
                    moved = moved || m;
                }
                live[u] = !moved;
            }
#pragma unroll
            for (int u = 0; u < UNR; u++) {
                if (live[u]) {
                    float a0, a1;
                    asm volatile("ld.shared.v2.f32 {%0,%1},[%2];"
                                 : "=f"(a0), "=f"(a1) : "r"(addr[u]));
                    a0 += v[u];
                    a1 += q[u];
                    asm volatile("st.shared.v2.f32 [%0],{%1,%2};"
                                 :: "r"(addr[u]), "f"(a0), "f"(a1) : "memory");
                }
            }
        }
    };

    const int nb = (begin < end) ? (end - begin) / UNR : 0;

#pragma unroll
    for (int j = 0; j < PIPE; j++)
        if (j < nb) stage(j, begin + j * UNR);

    int b = 0;
    for (; b + PIPE <= nb; b += PIPE) {
#pragma unroll
        for (int j = 0; j < PIPE; j++) {
            process(j);
            const int nxt = b + j + PIPE;
            if (nxt < nb) stage(j, begin + nxt * UNR);
        }
    }
#pragma unroll
    for (int j = 0; j < PIPE; j++)
        if (b + j < nb) process(j);

    for (int p = begin + nb * UNR; p < end; p++) {   // tail (<4 points)
        const int c0 = ci[p];
        const float vv = data[p * 64 + doff];
        const unsigned ad = sbase + ((unsigned)c0 << 8);
        float a0, a1;
        asm volatile("ld.shared.v2.f32 {%0,%1},[%2];" : "=f"(a0), "=f"(a1) : "r"(ad));
        a0 += vv;
        a1 = fmaf(vv, vv, a1);
        asm volatile("st.shared.v2.f32 [%0],{%1,%2};"
                     :: "r"(ad), "f"(a0), "f"(a1) : "memory");
    }
    __syncthreads();

    // Combine 8 warp tables. Slot (c, lane) of warp w: sm[w*WTBLF + c*64 + lane*2].
    // Even warps own dims [0,32), odd warps dims [32,64).
    for (int i = tid; i < Kc * 32; i += TPB) {
        const int c = i >> 5, l = i & 31;
        const int s = c * 64 + l * 2;
        float e = 0.f, o = 0.f, sq = 0.f;
#pragma unroll
        for (int ww = 0; ww < WPB; ww += 2) {
            e  += sm[ww * WTBLF + s];
            o  += sm[(ww + 1) * WTBLF + s];
            sq += sm[ww * WTBLF + s + 1] + sm[(ww + 1) * WTBLF + s + 1];
        }
        atomicAdd(&g_S1[c * Dc + l], e);
        atomicAdd(&g_S1[c * Dc + 32 + l], o);
        sm[s + 1] = sq;          // stash per-(c,lane) sq total in warp-0 table
    }
    __syncthreads();
    if (tid < Kc) {
        float sq = 0.f;
#pragma unroll
        for (int li = 0; li < 32; li++) {
            const int l = (li + tid) & 31;   // rotate to dodge bank conflicts
            sq += sm[tid * 64 + l * 2 + 1];
        }
        atomicAdd(&g_S2[tid], sq);
    }
}

// ---------------------------------------------------------------------------
// Kernel C: centroids + Si (accumulator re-zero moved to findb).
// ---------------------------------------------------------------------------
__global__ void finpre_kernel(float* __restrict__ out) {
    __shared__ float At[Dc * Kc];   // [d][c]
    const int tid = threadIdx.x;    // 512
    for (int i = tid; i < Kc * Dc; i += blockDim.x) {
        const int c = i / Dc, d = i - c * Dc;
        const float a = (0.001f + g_S1[i]) / (1.0f + g_cnt[c]);
        At[d * Kc + c] = a;
        g_At[d * Kc + c] = a;
    }
    __syncthreads();
    if (tid < Kc) {
        float nrm = 0.f, sa = 0.f;
#pragma unroll
        for (int d = 0; d < Dc; d++) {
            const float a = At[d * Kc + tid];
            nrm += a * a;
            sa  += a;
        }
        const float n  = g_cnt[tid];
        const float cs = 1.f + n;
        // dot(A, S1) = cs*|A|^2 - 0.001*sum(A)  (S1 = A*cs - 0.001 per dim)
        const float dot = cs * nrm - 0.001f * sa;
        const float val = (0.001f + g_S2[tid] - 2.f * dot + n * nrm) / cs;
        g_Si[tid] = sqrtf(fmaxf(val, 0.f));
    }
    if (tid == 0) out[0] = 0.f;
}

// ---------------------------------------------------------------------------
// Kernel D: one block per cluster row; row-max of Rij; atomic sum of maxima.
// Block c also re-zeroes accumulator slice c for the next graph replay.
// ---------------------------------------------------------------------------
__global__ void findb_kernel(float* __restrict__ out) {
    __shared__ float At[Dc * Kc];
    __shared__ float Sis[Kc];
    __shared__ float wmax[4];
    const int tid = threadIdx.x;    // 128
    const int c   = blockIdx.x;     // 0..99
    const float4* a4 = (const float4*)g_At;
    float4* s4 = (float4*)At;
    for (int i = tid; i < (Dc * Kc) >> 2; i += blockDim.x) s4[i] = a4[i];
    if (tid < Kc) Sis[tid] = g_Si[tid];
    // Re-zero this cluster's accumulator slice (read by finpre, done now).
    if (tid < Dc) g_S1[c * Dc + tid] = 0.f;
    if (tid == Dc) { g_S2[c] = 0.f; g_cnt[c] = 0.f; }
    __syncthreads();
    float m = 0.f;
    if (tid < Kc && tid != c) {
        const int j = tid;
        float ss = 0.f;
#pragma unroll
        for (int d = 0; d < Dc; d++) {
            const float df = At[d * Kc + c] - At[d * Kc + j];
            ss = fmaf(df, df, ss);
        }
        m = (Sis[c] + Sis[j]) / sqrtf(ss);
    }
#pragma unroll
    for (int o = 16; o > 0; o >>= 1) m = fmaxf(m, __shfl_xor_sync(~0u, m, o));
    if ((tid & 31) == 0) wmax[tid >> 5] = m;
    __syncthreads();
    if (tid == 0) {
        const float mm = fmaxf(fmaxf(wmax[0], wmax[1]), fmaxf(wmax[2], wmax[3]));
        atomicAdd(out, mm * (1.0f / (float)Kc));
    }
}

// ---------------------------------------------------------------------------
extern "C" void kernel_launch(void* const* d_in, const int* in_sizes, int n_in,
                              void* d_out, int out_size) {
    const float* data = (const float*)d_in[0];
    const int*   clus = (const int*)d_in[1];   // int32 labels (JAX x64 disabled)
    const int N = in_sizes[1];                 // 2,000,000

    const size_t smem = (size_t)(WPB * WTBLF) * sizeof(float);   // 204,800 B
    cudaFuncSetAttribute(pass1_kernel,
                         cudaFuncAttributeMaxDynamicSharedMemorySize, (int)smem);

    const int t1 = N / 3, t2 = (2 * N) / 3;
    hist_kernel  <<<NBLK, 256>>>(clus, 0,  t1);   // launches 1-3
    hist_kernel  <<<NBLK, 256>>>(clus, t1, t2);
    hist_kernel  <<<NBLK, 256>>>(clus, t2, N);
    pass1_kernel <<<NBLK, TPB, smem>>>(data, clus, N);  // 4th: ncu lands HERE
    finpre_kernel<<<1, 512>>>((float*)d_out);
    findb_kernel <<<Kc, 128>>>((float*)d_out);
}

// round 12
// speedup vs baseline: 3.3631x; 1.2501x over previous
#include <cuda_runtime.h>

// Problem constants (fixed shapes)
#define Kc    100
#define Dc    64
#define TPB   512            // 16 warps, 4 per SMSP
#define WPB   16
#define NPAIR 8              // warp pairs per block
#define NBLK  152
#define TOTP  (NBLK * NPAIR) // 1216 warp pairs
#define WTBLF (Kc * 32)      // floats per warp sum table (4B slot, lane=dim)
#define SQOFF (WPB * WTBLF)           // float offset of (sq,cnt) region: 51200
#define SMFLT (SQOFF + WPB * Kc * 2)  // 54400 floats = 217,600 B
#define UNR   4              // points per batch
#define PIPE  8              // batches in flight per warp

// Global scratch (zero-init at load; re-zeroed by findb each replay)
__device__ float g_S1[Kc * Dc];
__device__ float g_S2[Kc];
__device__ float g_cnt[Kc];
__device__ float g_At[Dc * Kc];   // centroids, transposed [d][c]
__device__ float g_Si[Kc];

__device__ __forceinline__ unsigned smem_u32(const void* p) {
    unsigned r;
    asm("{ .reg .u64 t; cvta.to.shared.u64 t, %1; cvt.u32.u64 %0, t; }"
        : "=r"(r) : "l"(p));
    return r;
}

// ---------------------------------------------------------------------------
// Kernel B: main streaming pass (counts folded in; no separate histogram).
// Warp pair (2w,2w+1): half=w&1 owns dims [half*32,half*32+32); lane owns ONE
// dim -> 4B sum slot. Per-batch |x|^2 totals via a 4-value butterfly;
// designated lanes {0,8,16,24} RMW the per-warp (sq,cnt) side table with one
// v2 access. Each warp of a pair adds 0.5 per point (pair total = 1.0).
// ---------------------------------------------------------------------------
__global__ __launch_bounds__(TPB, 1)
void pass1_kernel(const float* __restrict__ data,
                  const int* __restrict__ ci, int N) {
    extern __shared__ float sm[];
    const int tid  = threadIdx.x;
    const int w    = tid >> 5;
    const int lane = tid & 31;
    const int half = w & 1;

    float4* z = (float4*)sm;
    for (int i = tid; i < (SMFLT >> 2); i += TPB)
        z[i] = make_float4(0.f, 0.f, 0.f, 0.f);
    __syncthreads();

    const unsigned smb  = smem_u32(sm);
    const unsigned sumb = smb + (unsigned)w * (WTBLF * 4) + (unsigned)lane * 4;
    const unsigned sqb  = smb + SQOFF * 4 + (unsigned)w * (Kc * 8);

    const int gp    = blockIdx.x * NPAIR + (w >> 1);
    const int chunk = (((N + TOTP - 1) / TOTP) + 15) & ~15;  // 16-aligned
    const int begin = gp * chunk;
    const int end   = min(N, begin + chunk);
    const int doff  = half * 32 + lane;   // this thread's dim

    const bool b3 = (lane & 8) != 0, b4 = (lane & 16) != 0;
    const bool desig = (lane & 7) == 0;   // lanes 0,8,16,24

    int   cb[PIPE][UNR];
    float vb[PIPE][UNR];

    auto stage = [&](int j, int base) {
        const int4 cc = *(const int4*)&ci[base];   // 16B-aligned
        cb[j][0] = cc.x; cb[j][1] = cc.y; cb[j][2] = cc.z; cb[j][3] = cc.w;
#pragma unroll
        for (int u = 0; u < UNR; u++)
            vb[j][u] = data[(base + u) * 64 + doff];   // 128B/warp coalesced
    };

    auto process = [&](int j) {
        int*   c = cb[j];
        float* v = vb[j];
        float  r[UNR];
        unsigned addr[UNR];
#pragma unroll
        for (int u = 0; u < UNR; u++) {
            r[u]    = v[u] * v[u];                 // per-lane |x|^2 partial
            addr[u] = sumb + ((unsigned)c[u] << 7);
        }
        // 4-value butterfly: reduce r0..r3 across 32 lanes simultaneously.
        // Result: lanes 0-7 tot(r0), 8-15 tot(r2), 16-23 tot(r1), 24-31 tot(r3).
        float t, v01, v23, val;
        t   = __shfl_xor_sync(~0u, b4 ? r[0] : r[1], 16);
        v01 = (b4 ? r[1] : r[0]) + t;
        t   = __shfl_xor_sync(~0u, b4 ? r[2] : r[3], 16);
        v23 = (b4 ? r[3] : r[2]) + t;
        t   = __shfl_xor_sync(~0u, b3 ? v01 : v23, 8);
        val = (b3 ? v23 : v01) + t;
        val += __shfl_xor_sync(~0u, val, 4);
        val += __shfl_xor_sync(~0u, val, 2);
        val += __shfl_xor_sync(~0u, val, 1);

        bool clash = false;
#pragma unroll
        for (int u = 0; u < UNR - 1; u++)
#pragma unroll
            for (int k = u + 1; k < UNR; k++) clash |= (c[u] == c[k]);

        if (!clash) {   // distinct clusters: batch all LDS before any STS
            // designated lane's point: lane0->0, lane8->2, lane16->1, lane24->3
            const int cg = b4 ? (b3 ? c[3] : c[1]) : (b3 ? c[2] : c[0]);
            const unsigned sqa = sqb + (unsigned)cg * 8u;
            float a[UNR];
#pragma unroll
            for (int u = 0; u < UNR; u++)
                asm volatile("ld.shared.f32 %0,[%1];" : "=f"(a[u]) : "r"(addr[u]));
            float s0 = 0.f, s1 = 0.f;
            if (desig)
                asm volatile("ld.shared.v2.f32 {%0,%1},[%2];"
                             : "=f"(s0), "=f"(s1) : "r"(sqa));
#pragma unroll
            for (int u = 0; u < UNR; u++) a[u] += v[u];
            s0 += val;
            s1 += 0.5f;   // half per warp; pair total = 1.0 per point
#pragma unroll
            for (int u = 0; u < UNR; u++)
                asm volatile("st.shared.f32 [%0],%1;"
                             :: "r"(addr[u]), "f"(a[u]) : "memory");
            if (desig)
                asm volatile("st.shared.v2.f32 [%0],{%1,%2};"
                             :: "r"(sqa), "f"(s0), "f"(s1) : "memory");
        } else {        // rare (~6%): merge duplicates forward, serial chains
            float rt[UNR], cn[UNR];
            rt[0] = __shfl_sync(~0u, val, 0);
            rt[1] = __shfl_sync(~0u, val, 16);
            rt[2] = __shfl_sync(~0u, val, 8);
            rt[3] = __shfl_sync(~0u, val, 24);
#pragma unroll
            for (int u = 0; u < UNR; u++) cn[u] = 0.5f;  // half per warp
            bool live[UNR];
#pragma unroll
            for (int u = 0; u < UNR; u++) live[u] = true;
#pragma unroll
            for (int u = 0; u < UNR - 1; u++) {
                bool moved = false;
#pragma unroll
                for (int k = u + 1; k < UNR; k++) {
                    bool m = (c[u] == c[k]) && !moved;
                    if (m) { v[k] += v[u]; rt[k] += rt[u]; cn[k] += cn[u]; }
                    moved = moved || m;
                }
                live[u] = !moved;
            }
#pragma unroll
            for (int u = 0; u < UNR; u++) {
                if (live[u]) {
                    float a;
                    asm volatile("ld.shared.f32 %0,[%1];" : "=f"(a) : "r"(addr[u]));
                    a += v[u];
                    asm volatile("st.shared.f32 [%0],%1;"
                                 :: "r"(addr[u]), "f"(a) : "memory");
                    // collapsed all-lane v2 RMW (same addr, same values)
                    const unsigned sqa = sqb + (unsigned)c[u] * 8u;
                    float s0, s1;
                    asm volatile("ld.shared.v2.f32 {%0,%1},[%2];"
                                 : "=f"(s0), "=f"(s1) : "r"(sqa));
                    s0 += rt[u];
                    s1 += cn[u];
                    asm volatile("st.shared.v2.f32 [%0],{%1,%2};"
                                 :: "r"(sqa), "f"(s0), "f"(s1) : "memory");
                }
            }
        }
    };

    const int nb = (begin < end) ? (end - begin) / UNR : 0;

#pragma unroll
    for (int j = 0; j < PIPE; j++)
        if (j < nb) stage(j, begin + j * UNR);

    int b = 0;
    for (; b + PIPE <= nb; b += PIPE) {
#pragma unroll
        for (int j = 0; j < PIPE; j++) {
            process(j);
            const int nxt = b + j + PIPE;
            if (nxt < nb) stage(j, begin + nxt * UNR);
        }
    }
#pragma unroll
    for (int j = 0; j < PIPE; j++)
        if (b + j < nb) process(j);

    for (int p = begin + nb * UNR; p < end; p++) {   // tail (<4 points)
        const int c0 = ci[p];
        const float vv = data[p * 64 + doff];
        float rr = vv * vv;
#pragma unroll
        for (int o = 16; o > 0; o >>= 1)
            rr += __shfl_xor_sync(~0u, rr, o);
        const unsigned ad = sumb + ((unsigned)c0 << 7);
        float a;
        asm volatile("ld.shared.f32 %0,[%1];" : "=f"(a) : "r"(ad));
        a += vv;
        asm volatile("st.shared.f32 [%0],%1;" :: "r"(ad), "f"(a) : "memory");
        const unsigned sqa = sqb + (unsigned)c0 * 8u;   // all lanes same addr
        float s0, s1;
        asm volatile("ld.shared.v2.f32 {%0,%1},[%2];"
                     : "=f"(s0), "=f"(s1) : "r"(sqa));
        s0 += rr;
        s1 += 0.5f;   // half per warp; pair total = 1.0 per point
        asm volatile("st.shared.v2.f32 [%0],{%1,%2};"
                     :: "r"(sqa), "f"(s0), "f"(s1) : "memory");
    }
    __syncthreads();

    // Combine: S1[c][d] = sum over the 8 warps of parity (d>=32).
    for (int i = tid; i < Kc * Dc; i += TPB) {
        const int c = i >> 6, d = i & 63;
        const int par = (d >> 5), l = d & 31;
        float s = 0.f;
#pragma unroll
        for (int pp = 0; pp < NPAIR; pp++)
            s += sm[(pp * 2 + par) * WTBLF + c * 32 + l];
        atomicAdd(&g_S1[c * Dc + d], s);
    }
    // S2[c], cnt[c] from all 16 warps' (sq,cnt) tables.
    if (tid < Kc) {
        float s = 0.f, ct = 0.f;
#pragma unroll
        for (int ww = 0; ww < WPB; ww++) {
            s  += sm[SQOFF + ww * Kc * 2 + tid * 2];
            ct += sm[SQOFF + ww * Kc * 2 + tid * 2 + 1];
        }
        atomicAdd(&g_S2[tid], s);
        atomicAdd(&g_cnt[tid], ct);
    }
}

// ---------------------------------------------------------------------------
// Kernel C: centroids + Si (accumulator re-zero happens in findb).
// ---------------------------------------------------------------------------
__global__ void finpre_kernel(float* __restrict__ out) {
    __shared__ float At[Dc * Kc];   // [d][c]
    const int tid = threadIdx.x;    // 512
    for (int i = tid; i < Kc * Dc; i += blockDim.x) {
        const int c = i / Dc, d = i - c * Dc;
        const float a = (0.001f + g_S1[i]) / (1.0f + g_cnt[c]);
        At[d * Kc + c] = a;
        g_At[d * Kc + c] = a;
    }
    __syncthreads();
    if (tid < Kc) {
        float nrm = 0.f, sa = 0.f;
#pragma unroll
        for (int d = 0; d < Dc; d++) {
            const float a = At[d * Kc + tid];
            nrm += a * a;
            sa  += a;
        }
        const float n  = g_cnt[tid];
        const float cs = 1.f + n;
        // dot(A, S1) = cs*|A|^2 - 0.001*sum(A)  (S1 = A*cs - 0.001 per dim)
        const float dot = cs * nrm - 0.001f * sa;
        const float val = (0.001f + g_S2[tid] - 2.f * dot + n * nrm) / cs;
        g_Si[tid] = sqrtf(fmaxf(val, 0.f));
    }
    if (tid == 0) out[0] = 0.f;
}

// ---------------------------------------------------------------------------
// Kernel D: one block per cluster row; row-max of Rij; atomic sum of maxima.
// Block c also re-zeroes accumulator slice c for the next graph replay.
// ---------------------------------------------------------------------------
__global__ void findb_kernel(float* __restrict__ out) {
    __shared__ float At[Dc * Kc];
    __shared__ float Sis[Kc];
    __shared__ float wmax[4];
    const int tid = threadIdx.x;    // 128
    const int c   = blockIdx.x;     // 0..99
    const float4* a4 = (const float4*)g_At;
    float4* s4 = (float4*)At;
    for (int i = tid; i < (Dc * Kc) >> 2; i += blockDim.x) s4[i] = a4[i];
    if (tid < Kc) Sis[tid] = g_Si[tid];
    // Re-zero this cluster's accumulator slice (already consumed by finpre).
    if (tid < Dc) g_S1[c * Dc + tid] = 0.f;
    if (tid == Dc) { g_S2[c] = 0.f; g_cnt[c] = 0.f; }
    __syncthreads();
    float m = 0.f;
    if (tid < Kc && tid != c) {
        const int j = tid;
        float ss = 0.f;
#pragma unroll
        for (int d = 0; d < Dc; d++) {
            const float df = At[d * Kc + c] - At[d * Kc + j];
            ss = fmaf(df, df, ss);
        }
        m = (Sis[c] + Sis[j]) / sqrtf(ss);
    }
#pragma unroll
    for (int o = 16; o > 0; o >>= 1) m = fmaxf(m, __shfl_xor_sync(~0u, m, o));
    if ((tid & 31) == 0) wmax[tid >> 5] = m;
    __syncthreads();
    if (tid == 0) {
        const float mm = fmaxf(fmaxf(wmax[0], wmax[1]), fmaxf(wmax[2], wmax[3]));
        atomicAdd(out, mm * (1.0f / (float)Kc));
    }
}

// ---------------------------------------------------------------------------
extern "C" void kernel_launch(void* const* d_in, const int* in_sizes, int n_in,
                              void* d_out, int out_size) {
    const float* data = (const float*)d_in[0];
    const int*   clus = (const int*)d_in[1];   // int32 labels (JAX x64 disabled)
    const int N = in_sizes[1];                 // 2,000,000

    const size_t smem = (size_t)SMFLT * sizeof(float);   // 217,600 B
    cudaFuncSetAttribute(pass1_kernel,
                         cudaFuncAttributeMaxDynamicSharedMemorySize, (int)smem);

    pass1_kernel <<<NBLK, TPB, smem>>>(data, clus, N);
    finpre_kernel<<<1, 512>>>((float*)d_out);
    findb_kernel <<<Kc, 128>>>((float*)d_out);
}